// round 1
// baseline (speedup 1.0000x reference)
#include <cuda_runtime.h>
#include <cstdint>

#define H 128
#define MAXN 50000
#define BN_EPS 1e-5f

// ---------------- device scratch (static, no runtime allocation) -------------
__device__ float g_h[MAXN * H];    // current node features
__device__ float g_t[MAXN * H];    // temp (post-lin relu / z)
__device__ float g_agg[MAXN * H];  // (1+eps)*h + scatter-sum
__device__ float g_W[H * H];       // folded weight
__device__ float g_bias[H];        // folded bias

// ---------------- small utility kernels -------------------------------------
__global__ void zero_out_kernel(float* out, int n) {
    int i = blockIdx.x * blockDim.x + threadIdx.x;
    if (i < n) out[i] = 0.0f;
}

// h[n, :] = embed_table[x[n], :]
__global__ void embed_kernel(const int* __restrict__ x,
                             const float* __restrict__ table,
                             float* __restrict__ h, int Nn) {
    int i = blockIdx.x * blockDim.x + threadIdx.x;
    if (i >= Nn * (H / 4)) return;
    int n  = i >> 5;          // H/4 = 32 float4 per row
    int c4 = i & 31;
    int row = x[n];
    ((float4*)h)[(size_t)n * 32 + c4] =
        ((const float4*)table)[(size_t)row * 32 + c4];
}

// agg = (1 + eps[layer]) * t
__global__ void init_agg_kernel(const float* __restrict__ t,
                                const float* __restrict__ eps, int layer,
                                float* __restrict__ agg, int Nn) {
    int i = blockIdx.x * blockDim.x + threadIdx.x;
    if (i >= Nn * (H / 4)) return;
    float s = 1.0f + eps[layer];
    float4 v = ((const float4*)t)[i];
    v.x *= s; v.y *= s; v.z *= s; v.w *= s;
    ((float4*)agg)[i] = v;
}

// one warp per edge: agg[dst] += feat[src]  (vector atomic, 4 floats/lane)
__global__ void scatter_kernel(const float* __restrict__ feat,
                               const int* __restrict__ ei,
                               float* __restrict__ agg, int Ee) {
    int gi = blockIdx.x * blockDim.x + threadIdx.x;
    int e = gi >> 5;
    int lane = threadIdx.x & 31;
    if (e >= Ee) return;
    int src = __ldg(ei + e);
    int dst = __ldg(ei + Ee + e);
    float4 v = *(const float4*)(feat + (size_t)src * H + lane * 4);
    float* p = agg + (size_t)dst * H + lane * 4;
    asm volatile("red.global.add.v4.f32 [%0], {%1, %2, %3, %4};"
                 :: "l"(p), "f"(v.x), "f"(v.y), "f"(v.z), "f"(v.w)
                 : "memory");
}

// Fold pre-conv BatchNorm into lin weights:
//   y = relu(BN(h) @ W + b) = relu(h @ (diag(s)W) + (t@W + b))
__global__ void fold_pre_bn(const float* __restrict__ g, const float* __restrict__ b,
                            const float* __restrict__ m, const float* __restrict__ v,
                            const float* __restrict__ W, const float* __restrict__ lb,
                            float* __restrict__ Wo, float* __restrict__ bo) {
    __shared__ float s_s[H], s_t[H];
    int c = threadIdx.x;
    float sv = g[c] * rsqrtf(v[c] + BN_EPS);
    s_s[c] = sv;
    s_t[c] = b[c] - m[c] * sv;
    __syncthreads();
    int k = threadIdx.x;
    float acc = lb[k];
    for (int cc = 0; cc < H; cc++) {
        float w = W[cc * H + k];
        Wo[cc * H + k] = s_s[cc] * w;
        acc += s_t[cc] * w;
    }
    bo[k] = acc;
}

// Fold post-GEMM BatchNorm (over output channels) into mlp_w1:
//   relu(BN(z@W1 + b1)) = relu(z @ (W1 diag(s)) + (b1*s + t))
__global__ void fold_post_bn(const float* __restrict__ g, const float* __restrict__ b,
                             const float* __restrict__ m, const float* __restrict__ v,
                             const float* __restrict__ W, const float* __restrict__ lb,
                             float* __restrict__ Wo, float* __restrict__ bo) {
    int k = threadIdx.x;
    float sv = g[k] * rsqrtf(v[k] + BN_EPS);
    float tv = b[k] - m[k] * sv;
    bo[k] = lb[k] * sv + tv;
    for (int cc = 0; cc < H; cc++)
        Wo[cc * H + k] = W[cc * H + k] * sv;
}

// ---------------- SGEMM: C[M,128] = op(A[M,128] @ W[128,128] + bias) ---------
// BM=128, BN=128, BK=8, 256 threads, 8x8 microtile per thread.
template <bool RELU>
__global__ void __launch_bounds__(256)
gemm128_kernel(const float* __restrict__ A, const float* __restrict__ W,
               const float* __restrict__ bias, float* __restrict__ C, int M) {
    __shared__ float As[8][132];   // padded: transposed A tile
    __shared__ float Bs[8][128];

    const int tid = threadIdx.x;
    const int tx = tid & 15;   // col group (8 cols each)
    const int ty = tid >> 4;   // row group (8 rows each)
    const int m0 = blockIdx.x * 128;

    float acc[8][8];
#pragma unroll
    for (int i = 0; i < 8; i++)
#pragma unroll
        for (int j = 0; j < 8; j++) acc[i][j] = 0.0f;

    const int arow = tid >> 1;
    const int akq  = (tid & 1) * 4;
    const int brow = tid >> 5;
    const int bcol = (tid & 31) * 4;
    const int am = m0 + arow;
    const float* Aptr = A + (size_t)am * H;

    for (int kt = 0; kt < H; kt += 8) {
        float4 av = make_float4(0.f, 0.f, 0.f, 0.f);
        if (am < M) av = *(const float4*)(Aptr + kt + akq);
        As[akq + 0][arow] = av.x;
        As[akq + 1][arow] = av.y;
        As[akq + 2][arow] = av.z;
        As[akq + 3][arow] = av.w;
        *(float4*)&Bs[brow][bcol] =
            *(const float4*)(W + (size_t)(kt + brow) * H + bcol);
        __syncthreads();
#pragma unroll
        for (int kk = 0; kk < 8; kk++) {
            float a[8], b[8];
            *(float4*)(a)     = *(const float4*)&As[kk][ty * 8];
            *(float4*)(a + 4) = *(const float4*)&As[kk][ty * 8 + 4];
            *(float4*)(b)     = *(const float4*)&Bs[kk][tx * 8];
            *(float4*)(b + 4) = *(const float4*)&Bs[kk][tx * 8 + 4];
#pragma unroll
            for (int i = 0; i < 8; i++)
#pragma unroll
                for (int j = 0; j < 8; j++) acc[i][j] += a[i] * b[j];
        }
        __syncthreads();
    }

    float bi[8];
#pragma unroll
    for (int j = 0; j < 8; j++) bi[j] = bias[tx * 8 + j];

#pragma unroll
    for (int i = 0; i < 8; i++) {
        int m = m0 + ty * 8 + i;
        if (m < M) {
            float4 v0, v1;
            v0.x = acc[i][0] + bi[0]; v0.y = acc[i][1] + bi[1];
            v0.z = acc[i][2] + bi[2]; v0.w = acc[i][3] + bi[3];
            v1.x = acc[i][4] + bi[4]; v1.y = acc[i][5] + bi[5];
            v1.z = acc[i][6] + bi[6]; v1.w = acc[i][7] + bi[7];
            if (RELU) {
                v0.x = fmaxf(v0.x, 0.f); v0.y = fmaxf(v0.y, 0.f);
                v0.z = fmaxf(v0.z, 0.f); v0.w = fmaxf(v0.w, 0.f);
                v1.x = fmaxf(v1.x, 0.f); v1.y = fmaxf(v1.y, 0.f);
                v1.z = fmaxf(v1.z, 0.f); v1.w = fmaxf(v1.w, 0.f);
            }
            *(float4*)(C + (size_t)m * H + tx * 8)     = v0;
            *(float4*)(C + (size_t)m * H + tx * 8 + 4) = v1;
        }
    }
}

// readout: out[batch[n]] += h[n,:] @ ro_w + ro_b   (one warp per node)
__global__ void readout_kernel(const float* __restrict__ h,
                               const int* __restrict__ batch,
                               const float* __restrict__ w,
                               const float* __restrict__ rb,
                               float* __restrict__ out, int Nn) {
    __shared__ float ws[H];
    if (threadIdx.x < H) ws[threadIdx.x] = w[threadIdx.x];
    __syncthreads();
    int gi = blockIdx.x * blockDim.x + threadIdx.x;
    int n = gi >> 5;
    int lane = threadIdx.x & 31;
    if (n >= Nn) return;
    float4 hv = *(const float4*)(h + (size_t)n * H + lane * 4);
    float s = hv.x * ws[lane * 4] + hv.y * ws[lane * 4 + 1] +
              hv.z * ws[lane * 4 + 2] + hv.w * ws[lane * 4 + 3];
#pragma unroll
    for (int o = 16; o > 0; o >>= 1) s += __shfl_xor_sync(0xffffffff, s, o);
    if (lane == 0) atomicAdd(out + batch[n], s + rb[0]);
}

// ---------------- launcher ---------------------------------------------------
extern "C" void kernel_launch(void* const* d_in, const int* in_sizes, int n_in,
                              void* d_out, int out_size) {
    const int*   x      = (const int*)d_in[0];
    const int*   ei     = (const int*)d_in[1];
    const int*   batch  = (const int*)d_in[2];
    const float* table  = (const float*)d_in[3];
    const float* bn_g   = (const float*)d_in[4];
    const float* bn_b   = (const float*)d_in[5];
    const float* bn_m   = (const float*)d_in[6];
    const float* bn_v   = (const float*)d_in[7];
    const float* lin_w  = (const float*)d_in[8];
    const float* lin_b  = (const float*)d_in[9];
    const float* eps    = (const float*)d_in[10];
    const float* mlp_w1 = (const float*)d_in[11];
    const float* mlp_b1 = (const float*)d_in[12];
    const float* mbn_g  = (const float*)d_in[13];
    const float* mbn_b  = (const float*)d_in[14];
    const float* mbn_m  = (const float*)d_in[15];
    const float* mbn_v  = (const float*)d_in[16];
    const float* mlp_w2 = (const float*)d_in[17];
    const float* mlp_b2 = (const float*)d_in[18];
    const float* ro_w   = (const float*)d_in[19];
    const float* ro_b   = (const float*)d_in[20];

    const int Nn = in_sizes[0];
    const int Ee = in_sizes[1] / 2;
    const int Gg = out_size;

    float *h, *t, *agg, *Wf, *bf;
    cudaGetSymbolAddress((void**)&h,   g_h);
    cudaGetSymbolAddress((void**)&t,   g_t);
    cudaGetSymbolAddress((void**)&agg, g_agg);
    cudaGetSymbolAddress((void**)&Wf,  g_W);
    cudaGetSymbolAddress((void**)&bf,  g_bias);

    const int elem_grid = (Nn * (H / 4) + 255) / 256;
    const int gemm_grid = (Nn + 127) / 128;
    const int edge_grid = ((Ee * 32) + 255) / 256;

    zero_out_kernel<<<(Gg + 255) / 256, 256>>>((float*)d_out, Gg);
    embed_kernel<<<elem_grid, 256>>>(x, table, h, Nn);

    for (int l = 0; l < 3; l++) {
        // h := relu(BN(h) @ lin_w + lin_b)   [BN folded]
        fold_pre_bn<<<1, H>>>(bn_g + l * H, bn_b + l * H, bn_m + l * H,
                              bn_v + l * H, lin_w + (size_t)l * H * H,
                              lin_b + l * H, Wf, bf);
        gemm128_kernel<true><<<gemm_grid, 256>>>(h, Wf, bf, t, Nn);

        // agg := (1+eps)*h + scatter_sum(h[src] -> dst)
        init_agg_kernel<<<elem_grid, 256>>>(t, eps, l, agg, Nn);
        scatter_kernel<<<edge_grid, 256>>>(t, ei, agg, Ee);

        // z := relu(BN(agg @ mlp_w1 + b1))   [BN folded]
        fold_post_bn<<<1, H>>>(mbn_g + l * H, mbn_b + l * H, mbn_m + l * H,
                               mbn_v + l * H, mlp_w1 + (size_t)l * H * H,
                               mlp_b1 + l * H, Wf, bf);
        gemm128_kernel<true><<<gemm_grid, 256>>>(agg, Wf, bf, t, Nn);

        // h := z @ mlp_w2 + b2
        gemm128_kernel<false><<<gemm_grid, 256>>>(
            t, mlp_w2 + (size_t)l * H * H, mlp_b2 + l * H, h, Nn);
    }

    readout_kernel<<<elem_grid, 256>>>(h, batch, ro_w, ro_b, (float*)d_out, Nn);
}

// round 4
// speedup vs baseline: 1.0564x; 1.0564x over previous
#include <cuda_runtime.h>
#include <cstdint>

#define H 128
#define MAXN 50000
#define BN_EPS 1e-5f

#if defined(__CUDA_ARCH_FEAT_SM103_ALL) || defined(__CUDA_ARCH_FEAT_SM100_ALL)
#define HAS_TC5 1
#else
#define HAS_TC5 0
#endif

// ---------------- device scratch ---------------------------------------------
__device__ float g_h[MAXN * H];
__device__ float g_t[MAXN * H];
__device__ float g_agg[MAXN * H];
__device__ float g_Wf[6 * H * H];   // folded weights: slot = 2*layer + (0 pre,1 post)
__device__ float g_bf[6 * H];

// ---------------- PTX helpers -------------------------------------------------
__device__ __forceinline__ uint32_t smem_u32(const void* p) {
    uint32_t a;
    asm("{ .reg .u64 t; cvta.to.shared.u64 t, %1; cvt.u32.u64 %0, t; }" : "=r"(a) : "l"(p));
    return a;
}
__device__ __forceinline__ float tf32_hi(float x) {
    uint32_t r;
    asm("cvt.rna.tf32.f32 %0, %1;" : "=r"(r) : "f"(x));
    return __uint_as_float(r);
}

#if HAS_TC5
__device__ __forceinline__ void mma_tf32_ss(uint32_t d, uint64_t a, uint64_t b,
                                            uint32_t idesc, uint32_t en) {
    asm volatile(
        "{\n\t.reg .pred p;\n\t"
        "setp.ne.u32 p, %5, 0;\n\t"
        "tcgen05.mma.cta_group::1.kind::tf32 [%0], %1, %2, %3, {%4, %4, %4, %4}, p;\n\t}"
        :: "r"(d), "l"(a), "l"(b), "r"(idesc), "r"(0u), "r"(en) : "memory");
}
#define MBAR_INIT(a, c)  asm volatile("mbarrier.init.shared.b64 [%0], %1;" :: "r"(a), "r"(c) : "memory")
#define MBAR_WAIT(a, ph) do {                                                               \
    asm volatile("{\n\t.reg .pred P1;\n\tWL_%=:\n\t"                                        \
        "mbarrier.try_wait.parity.acquire.cta.shared::cta.b64 P1, [%0], %1, 0x989680;\n\t"  \
        "@P1 bra.uni WD_%=;\n\tbra.uni WL_%=;\n\tWD_%=:\n\t}"                               \
        :: "r"(a), "r"(ph) : "memory");                                                     \
} while (0)
#define TC_ALLOC(sa, n)  asm volatile("tcgen05.alloc.cta_group::1.sync.aligned.shared::cta.b32 [%0], %1;" :: "r"(sa), "r"(n) : "memory")
#define TC_DEALLOC(t, n) asm volatile("tcgen05.dealloc.cta_group::1.sync.aligned.b32 %0, %1;" :: "r"(t), "r"(n))
#define TC_RELINQ()      asm volatile("tcgen05.relinquish_alloc_permit.cta_group::1.sync.aligned;")
#define TC_COMMIT(mb)    asm volatile("tcgen05.commit.cta_group::1.mbarrier::arrive::one.shared::cluster.b64 [%0];" :: "r"(mb) : "memory")
#define TC_FENCE_AFTER() asm volatile("tcgen05.fence::after_thread_sync;" ::: "memory")
#define TC_WAIT_LD()     asm volatile("tcgen05.wait::ld.sync.aligned;" ::: "memory")
#define FENCE_ASYNC()    asm volatile("fence.proxy.async.shared::cta;" ::: "memory")
#define LDTM_X32(r, ta)                                                      \
    asm volatile("tcgen05.ld.sync.aligned.32x32b.x32.b32 "                   \
        "{%0,%1,%2,%3,%4,%5,%6,%7,%8,%9,%10,%11,%12,%13,%14,%15,"            \
        "%16,%17,%18,%19,%20,%21,%22,%23,%24,%25,%26,%27,%28,%29,%30,%31},"  \
        "[%32];"                                                             \
        : "=r"((r)[0]),"=r"((r)[1]),"=r"((r)[2]),"=r"((r)[3]),               \
          "=r"((r)[4]),"=r"((r)[5]),"=r"((r)[6]),"=r"((r)[7]),               \
          "=r"((r)[8]),"=r"((r)[9]),"=r"((r)[10]),"=r"((r)[11]),             \
          "=r"((r)[12]),"=r"((r)[13]),"=r"((r)[14]),"=r"((r)[15]),           \
          "=r"((r)[16]),"=r"((r)[17]),"=r"((r)[18]),"=r"((r)[19]),           \
          "=r"((r)[20]),"=r"((r)[21]),"=r"((r)[22]),"=r"((r)[23]),           \
          "=r"((r)[24]),"=r"((r)[25]),"=r"((r)[26]),"=r"((r)[27]),           \
          "=r"((r)[28]),"=r"((r)[29]),"=r"((r)[30]),"=r"((r)[31])            \
        : "r"(ta))
#endif  // HAS_TC5

// SW128 K-major smem descriptor base: layout=2, version=1, SBO=64, LBO=1
static constexpr uint64_t DESC_BASE =
    (2ULL << 61) | (1ULL << 46) | (64ULL << 32) | (1ULL << 16);
__device__ __forceinline__ uint64_t mk_desc(uint32_t addr) {
    return DESC_BASE | ((uint64_t)(addr >> 4) & 0x3FFF);
}
// idesc: cF32 | aTF32 | bTF32 | N=128 | M=128  (K-major A & B)
static constexpr uint32_t IDESC =
    (1u << 4) | (2u << 7) | (2u << 10) | (16u << 17) | (8u << 24);

// blocked-atom SW128 address for a [128 rows x 64 f32] K-major chunk tile
// atom = 8 rows x 32 f32 (128B); atom_off = atom_row + atom_col*16
__device__ __forceinline__ uint32_t tile_addr(int row, int col) {
    uint32_t b = ((uint32_t)(row >> 3) << 10) + ((uint32_t)(col >> 5) << 14) +
                 ((uint32_t)(row & 7) << 7) + ((uint32_t)(col & 31) << 2);
    return b ^ ((b >> 3) & 0x70);
}

// ---------------- smem layout --------------------------------------------------
static constexpr int SM_TPTR = 0;
static constexpr int SM_MBAR = 8;
static constexpr int SM_BIAS = 16;          // 128 f32
static constexpr int SM_RO   = 528;         // 128 f32
static constexpr int SM_AHI  = 2048;        // 32KB each
static constexpr int SM_ALO  = SM_AHI + 32768;
static constexpr int SM_BHI  = SM_ALO + 32768;
static constexpr int SM_BLO  = SM_BHI + 32768;
static constexpr int SM_TOTAL = SM_BLO + 32768;   // 133120 B

// ---------------- small kernels -------------------------------------------------
__global__ void zero_out_kernel(float* out, int n) {
    int i = blockIdx.x * blockDim.x + threadIdx.x;
    if (i < n) out[i] = 0.0f;
}

__global__ void fold_all_kernel(
    const float* __restrict__ bn_g, const float* __restrict__ bn_b,
    const float* __restrict__ bn_m, const float* __restrict__ bn_v,
    const float* __restrict__ lin_w, const float* __restrict__ lin_b,
    const float* __restrict__ mbn_g, const float* __restrict__ mbn_b,
    const float* __restrict__ mbn_m, const float* __restrict__ mbn_v,
    const float* __restrict__ mlp_w1, const float* __restrict__ mlp_b1,
    float* __restrict__ Wo, float* __restrict__ bo) {
    int slot = blockIdx.x;            // 0..5
    int l = slot >> 1;
    int k = threadIdx.x;
    float* W_out = Wo + (size_t)slot * H * H;
    float* b_out = bo + slot * H;
    if ((slot & 1) == 0) {
        // pre-BN fold into lin (input-channel scale)
        __shared__ float ss[H], st[H];
        float sv = bn_g[l * H + k] * rsqrtf(bn_v[l * H + k] + BN_EPS);
        ss[k] = sv;
        st[k] = bn_b[l * H + k] - bn_m[l * H + k] * sv;
        __syncthreads();
        const float* W = lin_w + (size_t)l * H * H;
        float acc = lin_b[l * H + k];
        for (int cc = 0; cc < H; cc++) {
            float w = W[cc * H + k];
            W_out[cc * H + k] = ss[cc] * w;
            acc += st[cc] * w;
        }
        b_out[k] = acc;
    } else {
        // post-BN fold into mlp_w1 (output-channel scale)
        float sv = mbn_g[l * H + k] * rsqrtf(mbn_v[l * H + k] + BN_EPS);
        float tv = mbn_b[l * H + k] - mbn_m[l * H + k] * sv;
        b_out[k] = mlp_b1[l * H + k] * sv + tv;
        const float* W = mlp_w1 + (size_t)l * H * H;
        for (int cc = 0; cc < H; cc++)
            W_out[cc * H + k] = W[cc * H + k] * sv;
    }
}

// one warp per edge: agg[dst] += feat[src]
__global__ void scatter_kernel(const float* __restrict__ feat,
                               const int* __restrict__ ei,
                               float* __restrict__ agg, int Ee) {
    int gi = blockIdx.x * blockDim.x + threadIdx.x;
    int e = gi >> 5;
    int lane = threadIdx.x & 31;
    if (e >= Ee) return;
    int src = __ldg(ei + e);
    int dst = __ldg(ei + Ee + e);
    float4 v = *(const float4*)(feat + (size_t)src * H + lane * 4);
    float* p = agg + (size_t)dst * H + lane * 4;
    asm volatile("red.global.add.v4.f32 [%0], {%1, %2, %3, %4};"
                 :: "l"(p), "f"(v.x), "f"(v.y), "f"(v.z), "f"(v.w) : "memory");
}

// ---------------- GEMM: C[M,128] = op(A[M,128] @ W[128,128] + b) ----------------
// tcgen05 3xtf32 on sm_103a; SIMT FFMA fallback on plain sm_103.
template <bool RELU, bool WAGG, bool RDOUT, bool GATH>
__global__ void __launch_bounds__(256)
gemm_tc(const float* __restrict__ A, const int* __restrict__ gather,
        const float* __restrict__ Wp, const float* __restrict__ bias,
        float* __restrict__ C, float* __restrict__ Agg,
        const float* __restrict__ eps, int layer,
        const int* __restrict__ batch, const float* __restrict__ ro_w,
        const float* __restrict__ ro_b, float* __restrict__ gout, int M) {
    extern __shared__ char smem[];
    const int tid = threadIdx.x;
    const int m0 = blockIdx.x * 128;

    float* sBias = (float*)(smem + SM_BIAS);
    float* sRo   = (float*)(smem + SM_RO);
    if (tid < H) {
        sBias[tid] = bias[tid];
        if (RDOUT) sRo[tid] = ro_w[tid];
    }

#if HAS_TC5
    // ===================== tcgen05 path (sm_103a) ==============================
    const uint32_t sbase = smem_u32(smem);
    const int wid = tid >> 5, lid = tid & 31;
    if (wid == 0) {
        TC_ALLOC(sbase + SM_TPTR, 128);
        TC_RELINQ();
    }
    if (tid == 0) MBAR_INIT(sbase + SM_MBAR, 1);
    __syncthreads();
    uint32_t tmem;
    asm volatile("ld.shared.b32 %0, [%1];" : "=r"(tmem) : "r"(sbase + SM_TPTR));

    for (int kc = 0; kc < 2; kc++) {
        // ---- A chunk [128 x 64], hi/lo split, swizzled float4 stores ----
#pragma unroll
        for (int i = 0; i < 8; i++) {
            int idx = tid + i * 256;          // 0..2047 float4s
            int row = idx >> 4;
            int cb  = (idx & 15) * 4;
            int m = m0 + row;
            float4 v = make_float4(0.f, 0.f, 0.f, 0.f);
            if (m < M) {
                const float* src;
                if (GATH) src = A + (size_t)__ldg(gather + m) * H;
                else      src = A + (size_t)m * H;
                v = *(const float4*)(src + kc * 64 + cb);
            }
            float4 hi, lo;
            hi.x = tf32_hi(v.x); lo.x = v.x - hi.x;
            hi.y = tf32_hi(v.y); lo.y = v.y - hi.y;
            hi.z = tf32_hi(v.z); lo.z = v.z - hi.z;
            hi.w = tf32_hi(v.w); lo.w = v.w - hi.w;
            uint32_t off = tile_addr(row, cb);
            *(float4*)(smem + SM_AHI + off) = hi;
            *(float4*)(smem + SM_ALO + off) = lo;
        }
        // ---- B chunk = W[kc*64 .. +64, 0..128] transposed to [n][k] ----
#pragma unroll
        for (int i = 0; i < 8; i++) {
            int idx = tid + i * 256;
            int k  = idx >> 5;                // 0..63
            int n4 = (idx & 31) * 4;          // 0..124
            float4 v = *(const float4*)(Wp + (size_t)(kc * 64 + k) * H + n4);
            float e[4] = {v.x, v.y, v.z, v.w};
#pragma unroll
            for (int j = 0; j < 4; j++) {
                float hi = tf32_hi(e[j]);
                uint32_t off = tile_addr(n4 + j, k);
                *(float*)(smem + SM_BHI + off) = hi;
                *(float*)(smem + SM_BLO + off) = e[j] - hi;
            }
        }
        FENCE_ASYNC();
        __syncthreads();

        if (tid == 0) {
            uint64_t ah = mk_desc(sbase + SM_AHI);
            uint64_t al = mk_desc(sbase + SM_ALO);
            uint64_t bh = mk_desc(sbase + SM_BHI);
            uint64_t bl = mk_desc(sbase + SM_BLO);
            uint32_t en = (kc == 0) ? 0u : 1u;
#pragma unroll
            for (int s = 0; s < 8; s++) {
                uint64_t off = (uint64_t)((s >> 2) * 1024 + (s & 3) * 2);
                mma_tf32_ss(tmem, ah + off, bh + off, IDESC, en); en = 1u;
                mma_tf32_ss(tmem, ah + off, bl + off, IDESC, 1u);
                mma_tf32_ss(tmem, al + off, bh + off, IDESC, 1u);
            }
            TC_COMMIT(sbase + SM_MBAR);
        }
        MBAR_WAIT(sbase + SM_MBAR, (uint32_t)kc);
    }
    TC_FENCE_AFTER();

    // ---- epilogue: warp -> rows (wid&3)*32+lid, col half (wid>>2) ----
    const int m = m0 + (wid & 3) * 32 + lid;
    const int cbase = (wid >> 2) * 64;
    float ep = 0.f;
    if (WAGG) ep = 1.0f + __ldg(eps + layer);
    float dotv = 0.f;
#pragma unroll
    for (int hh = 0; hh < 2; hh++) {
        uint32_t r[32];
        LDTM_X32(r, tmem + cbase + hh * 32);
        TC_WAIT_LD();
        if (m < M) {
            const int c0 = cbase + hh * 32;
#pragma unroll
            for (int j = 0; j < 8; j++) {
                int c = c0 + j * 4;
                float4 o;
                o.x = __uint_as_float(r[j * 4 + 0]) + sBias[c + 0];
                o.y = __uint_as_float(r[j * 4 + 1]) + sBias[c + 1];
                o.z = __uint_as_float(r[j * 4 + 2]) + sBias[c + 2];
                o.w = __uint_as_float(r[j * 4 + 3]) + sBias[c + 3];
                if (RELU) {
                    o.x = fmaxf(o.x, 0.f); o.y = fmaxf(o.y, 0.f);
                    o.z = fmaxf(o.z, 0.f); o.w = fmaxf(o.w, 0.f);
                }
                *(float4*)(C + (size_t)m * H + c) = o;
                if (WAGG) {
                    float4 a;
                    a.x = o.x * ep; a.y = o.y * ep; a.z = o.z * ep; a.w = o.w * ep;
                    *(float4*)(Agg + (size_t)m * H + c) = a;
                }
                if (RDOUT) {
                    dotv += o.x * sRo[c] + o.y * sRo[c + 1] +
                            o.z * sRo[c + 2] + o.w * sRo[c + 3];
                }
            }
        }
    }
    if (RDOUT && m < M) {
        if (cbase == 0) dotv += __ldg(ro_b);
        atomicAdd(gout + __ldg(batch + m), dotv);
    }
    __syncthreads();
    if (wid == 0) TC_DEALLOC(tmem, 128);

#else
    // ===================== SIMT FFMA fallback (plain sm_103) ====================
    float (*As)[132] = (float(*)[132])(smem + SM_AHI);  // [8][132]
    float (*Bs)[128] = (float(*)[128])(smem + SM_BHI);  // [8][128]
    __syncthreads();

    const int tx = tid & 15;
    const int ty = tid >> 4;

    float acc[8][8];
#pragma unroll
    for (int i = 0; i < 8; i++)
#pragma unroll
        for (int j = 0; j < 8; j++) acc[i][j] = 0.0f;

    const int arow = tid >> 1;
    const int akq  = (tid & 1) * 4;
    const int brow = tid >> 5;
    const int bcol = (tid & 31) * 4;
    const int am = m0 + arow;
    const float* Aptr = nullptr;
    if (am < M) {
        if (GATH) Aptr = A + (size_t)__ldg(gather + am) * H;
        else      Aptr = A + (size_t)am * H;
    }

    for (int kt = 0; kt < H; kt += 8) {
        float4 av = make_float4(0.f, 0.f, 0.f, 0.f);
        if (Aptr) av = *(const float4*)(Aptr + kt + akq);
        As[akq + 0][arow] = av.x;
        As[akq + 1][arow] = av.y;
        As[akq + 2][arow] = av.z;
        As[akq + 3][arow] = av.w;
        *(float4*)&Bs[brow][bcol] =
            *(const float4*)(Wp + (size_t)(kt + brow) * H + bcol);
        __syncthreads();
#pragma unroll
        for (int kk = 0; kk < 8; kk++) {
            float a[8], b[8];
            *(float4*)(a)     = *(const float4*)&As[kk][ty * 8];
            *(float4*)(a + 4) = *(const float4*)&As[kk][ty * 8 + 4];
            *(float4*)(b)     = *(const float4*)&Bs[kk][tx * 8];
            *(float4*)(b + 4) = *(const float4*)&Bs[kk][tx * 8 + 4];
#pragma unroll
            for (int i = 0; i < 8; i++)
#pragma unroll
                for (int j = 0; j < 8; j++) acc[i][j] += a[i] * b[j];
        }
        __syncthreads();
    }

    float ep = 0.f;
    if (WAGG) ep = 1.0f + __ldg(eps + layer);
    float bi[8], rw[8];
#pragma unroll
    for (int j = 0; j < 8; j++) {
        bi[j] = sBias[tx * 8 + j];
        if (RDOUT) rw[j] = sRo[tx * 8 + j];
    }

#pragma unroll
    for (int i = 0; i < 8; i++) {
        int m = m0 + ty * 8 + i;
        float o[8];
#pragma unroll
        for (int j = 0; j < 8; j++) {
            o[j] = acc[i][j] + bi[j];
            if (RELU) o[j] = fmaxf(o[j], 0.f);
        }
        if (m < M) {
            *(float4*)(C + (size_t)m * H + tx * 8)     = *(float4*)(o);
            *(float4*)(C + (size_t)m * H + tx * 8 + 4) = *(float4*)(o + 4);
            if (WAGG) {
                float a2[8];
#pragma unroll
                for (int j = 0; j < 8; j++) a2[j] = o[j] * ep;
                *(float4*)(Agg + (size_t)m * H + tx * 8)     = *(float4*)(a2);
                *(float4*)(Agg + (size_t)m * H + tx * 8 + 4) = *(float4*)(a2 + 4);
            }
        }
        if (RDOUT) {
            float dv = 0.f;
            if (m < M) {
#pragma unroll
                for (int j = 0; j < 8; j++) dv += o[j] * rw[j];
            }
#pragma unroll
            for (int off = 8; off > 0; off >>= 1)
                dv += __shfl_xor_sync(0xffffffff, dv, off);
            if (tx == 0 && m < M)
                atomicAdd(gout + __ldg(batch + m), dv + __ldg(ro_b));
        }
    }
#endif
}

// ---------------- launcher ------------------------------------------------------
extern "C" void kernel_launch(void* const* d_in, const int* in_sizes, int n_in,
                              void* d_out, int out_size) {
    const int*   x      = (const int*)d_in[0];
    const int*   ei     = (const int*)d_in[1];
    const int*   batch  = (const int*)d_in[2];
    const float* table  = (const float*)d_in[3];
    const float* bn_g   = (const float*)d_in[4];
    const float* bn_b   = (const float*)d_in[5];
    const float* bn_m   = (const float*)d_in[6];
    const float* bn_v   = (const float*)d_in[7];
    const float* lin_w  = (const float*)d_in[8];
    const float* lin_b  = (const float*)d_in[9];
    const float* eps    = (const float*)d_in[10];
    const float* mlp_w1 = (const float*)d_in[11];
    const float* mlp_b1 = (const float*)d_in[12];
    const float* mbn_g  = (const float*)d_in[13];
    const float* mbn_b  = (const float*)d_in[14];
    const float* mbn_m  = (const float*)d_in[15];
    const float* mbn_v  = (const float*)d_in[16];
    const float* mlp_w2 = (const float*)d_in[17];
    const float* mlp_b2 = (const float*)d_in[18];
    const float* ro_w   = (const float*)d_in[19];
    const float* ro_b   = (const float*)d_in[20];

    const int Nn = in_sizes[0];
    const int Ee = in_sizes[1] / 2;
    const int Gg = out_size;

    float *h, *t, *agg, *Wf, *bf;
    cudaGetSymbolAddress((void**)&h,   g_h);
    cudaGetSymbolAddress((void**)&t,   g_t);
    cudaGetSymbolAddress((void**)&agg, g_agg);
    cudaGetSymbolAddress((void**)&Wf,  g_Wf);
    cudaGetSymbolAddress((void**)&bf,  g_bf);

    cudaFuncSetAttribute(gemm_tc<true,  true,  false, true >, cudaFuncAttributeMaxDynamicSharedMemorySize, SM_TOTAL);
    cudaFuncSetAttribute(gemm_tc<true,  true,  false, false>, cudaFuncAttributeMaxDynamicSharedMemorySize, SM_TOTAL);
    cudaFuncSetAttribute(gemm_tc<true,  false, false, false>, cudaFuncAttributeMaxDynamicSharedMemorySize, SM_TOTAL);
    cudaFuncSetAttribute(gemm_tc<false, false, false, false>, cudaFuncAttributeMaxDynamicSharedMemorySize, SM_TOTAL);
    cudaFuncSetAttribute(gemm_tc<false, false, true,  false>, cudaFuncAttributeMaxDynamicSharedMemorySize, SM_TOTAL);

    const int gemm_grid = (Nn + 127) / 128;
    const int edge_grid = ((Ee * 32) + 255) / 256;

    zero_out_kernel<<<(Gg + 255) / 256, 256>>>((float*)d_out, Gg);
    fold_all_kernel<<<6, H>>>(bn_g, bn_b, bn_m, bn_v, lin_w, lin_b,
                              mbn_g, mbn_b, mbn_m, mbn_v, mlp_w1, mlp_b1, Wf, bf);

    for (int l = 0; l < 3; l++) {
        const float* W1 = Wf + (size_t)(2 * l) * H * H;
        const float* b1 = bf + (2 * l) * H;
        const float* W2 = Wf + (size_t)(2 * l + 1) * H * H;
        const float* b2 = bf + (2 * l + 1) * H;

        // t := relu(BN(h) @ lin + b); agg := (1+eps)*t   (fused)
        if (l == 0)
            gemm_tc<true, true, false, true><<<gemm_grid, 256, SM_TOTAL>>>(
                table, x, W1, b1, t, agg, eps, l, nullptr, nullptr, nullptr, nullptr, Nn);
        else
            gemm_tc<true, true, false, false><<<gemm_grid, 256, SM_TOTAL>>>(
                h, nullptr, W1, b1, t, agg, eps, l, nullptr, nullptr, nullptr, nullptr, Nn);

        // agg += scatter_sum(t[src] -> dst)
        scatter_kernel<<<edge_grid, 256>>>(t, ei, agg, Ee);

        // t := relu(BN(agg @ mlp_w1 + b1))
        gemm_tc<true, false, false, false><<<gemm_grid, 256, SM_TOTAL>>>(
            agg, nullptr, W2, b2, t, nullptr, nullptr, 0, nullptr, nullptr, nullptr, nullptr, Nn);

        // h := t @ mlp_w2 + b2  (+ fused readout on last layer)
        if (l == 2)
            gemm_tc<false, false, true, false><<<gemm_grid, 256, SM_TOTAL>>>(
                t, nullptr, mlp_w2 + (size_t)l * H * H, mlp_b2 + l * H, h, nullptr,
                nullptr, 0, batch, ro_w, ro_b, (float*)d_out, Nn);
        else
            gemm_tc<false, false, false, false><<<gemm_grid, 256, SM_TOTAL>>>(
                t, nullptr, mlp_w2 + (size_t)l * H * H, mlp_b2 + l * H, h, nullptr,
                nullptr, 0, nullptr, nullptr, nullptr, nullptr, Nn);
    }
}